// round 3
// baseline (speedup 1.0000x reference)
#include <cuda_runtime.h>

#define B_ 4
#define S_ 2048
#define D_ 1024
#define H_ 16
#define DK_ 64
#define DV_ 64
#define DOUT_ 1024

// Scratch: qh/kh/vh in (b,h,s,e) layout; concat in (b,s,h*DV) layout.
__device__ float g_qh[(size_t)B_*H_*S_*DK_];
__device__ float g_kh[(size_t)B_*H_*S_*DK_];
__device__ float g_vh[(size_t)B_*H_*S_*DV_];
__device__ float g_cat[(size_t)B_*S_*H_*DV_];

// ---------------------------------------------------------------------------
// Kernel 1: per-head projections.  For z in {0,1,2} (q,k,v):
//   Out[b,h,s,e] = sum_d X[b,s,d] * W[h,d,e] + bias[h,e]
// GEMM tile: BM=64 (s), BN=64 (=DK), BK=16 (d).  256 threads, 4x4 micro-tile.
// ---------------------------------------------------------------------------
__global__ __launch_bounds__(256) void proj_kernel(
    const float* __restrict__ q, const float* __restrict__ k, const float* __restrict__ v,
    const float* __restrict__ Wq, const float* __restrict__ Wk, const float* __restrict__ Wv,
    const float* __restrict__ bq, const float* __restrict__ bk, const float* __restrict__ bv)
{
    const int z = blockIdx.z;
    const float* X    = (z == 0) ? q  : (z == 1) ? k  : v;
    const float* W    = (z == 0) ? Wq : (z == 1) ? Wk : Wv;
    const float* bias = (z == 0) ? bq : (z == 1) ? bk : bv;
    float* Out        = (z == 0) ? g_qh : (z == 1) ? g_kh : g_vh;

    const int bh = blockIdx.y;
    const int h = bh & 15;
    const int s0 = blockIdx.x * 64;
    const int b = bh >> 4;

    const float* Xb = X + ((size_t)b * S_ + s0) * D_;
    const float* Wh = W + (size_t)h * D_ * DK_;
    float* Ob = Out + ((size_t)bh * S_ + s0) * DK_;

    __shared__ float As[16][64];   // As[kk][m]  (A transposed)
    __shared__ float Bs[16][64];   // Bs[kk][n]

    const int tid = threadIdx.x;
    const int tx = tid & 15, ty = tid >> 4;
    const int arow = tid >> 2, aseg = (tid & 3) * 4;   // A loader: 64 rows x 4 float4-segments
    const int brow = tid >> 4, bseg = (tid & 15) * 4;  // B loader: 16 rows x 16 float4-segments

    float acc[4][4] = {};

    for (int kk = 0; kk < D_; kk += 16) {
        float4 a4 = *(const float4*)(Xb + (size_t)arow * D_ + kk + aseg);
        As[aseg + 0][arow] = a4.x;
        As[aseg + 1][arow] = a4.y;
        As[aseg + 2][arow] = a4.z;
        As[aseg + 3][arow] = a4.w;
        *(float4*)(&Bs[brow][bseg]) = *(const float4*)(Wh + (size_t)(kk + brow) * DK_ + bseg);
        __syncthreads();
#pragma unroll
        for (int p = 0; p < 16; ++p) {
            float4 a = *(const float4*)(&As[p][ty * 4]);
            float4 bb = *(const float4*)(&Bs[p][tx * 4]);
            float ar[4] = {a.x, a.y, a.z, a.w};
            float br[4] = {bb.x, bb.y, bb.z, bb.w};
#pragma unroll
            for (int i = 0; i < 4; ++i)
#pragma unroll
                for (int j = 0; j < 4; ++j)
                    acc[i][j] = fmaf(ar[i], br[j], acc[i][j]);
        }
        __syncthreads();
    }

#pragma unroll
    for (int i = 0; i < 4; ++i)
#pragma unroll
        for (int j = 0; j < 4; ++j)
            Ob[(size_t)(ty * 4 + i) * DK_ + tx * 4 + j] =
                acc[i][j] + bias[h * DK_ + tx * 4 + j];
}

// ---------------------------------------------------------------------------
// Kernel 2: flash-style attention per (b,h).  Block = 32 query rows.
// Key chunks of 64.  Online softmax with running max/denominator.
// Mask is int32 (harness converts bool -> int32).
// Writes concat layout g_cat[b, s, h*DV + e].
// ---------------------------------------------------------------------------
__global__ __launch_bounds__(256) void attn_kernel(const int* __restrict__ mask)
{
    const int bh = blockIdx.y;
    const int b = bh >> 4, h = bh & 15;
    const int q0 = blockIdx.x * 32;

    const float* Qg = g_qh + ((size_t)bh * S_ + q0) * DK_;
    const float* Kg = g_kh + (size_t)bh * S_ * DK_;
    const float* Vg = g_vh + (size_t)bh * S_ * DK_;
    const int* mk = mask + (size_t)b * S_;

    __shared__ float Qs[32][64];    // [q][e], natural layout
    __shared__ float KV[64][64];    // K phase: KV[e][kcol] (K^T); V phase: KV[k][e]
    __shared__ float Ss[32][64];    // scores / probabilities
    __shared__ float mrow[32], lrow[32], frow[32];

    const int tid = threadIdx.x;
    const int tx = tid & 15, ty = tid >> 4;    // compute mapping: rows ty*2+i, cols tx*4+j
    const int srow = tid >> 3, oct = tid & 7;  // softmax mapping: 8 threads per row

    // Load Q tile (scaled by 1/sqrt(DK) = 0.125)
    for (int i = tid; i < 32 * 16; i += 256) {
        int row = i >> 4;
        int e4 = (i & 15) * 4;
        float4 v4 = *(const float4*)(Qg + (size_t)row * DK_ + e4);
        *(float4*)(&Qs[row][e4]) = make_float4(v4.x * 0.125f, v4.y * 0.125f,
                                               v4.z * 0.125f, v4.w * 0.125f);
    }
    if (tid < 32) { mrow[tid] = -1e30f; lrow[tid] = 0.0f; }

    float oacc[2][4] = {};

    for (int kc = 0; kc < S_; kc += 64) {
        __syncthreads();   // previous-iter Ss/KV consumers done

        // Load K chunk transposed: KV[e][kcol].
        for (int i = tid; i < 64 * 16; i += 256) {
            int row = i & 63;            // kcol
            int e4 = (i >> 6) * 4;
            float4 v4 = *(const float4*)(Kg + (size_t)(kc + row) * DK_ + e4);
            KV[e4 + 0][row] = v4.x;
            KV[e4 + 1][row] = v4.y;
            KV[e4 + 2][row] = v4.z;
            KV[e4 + 3][row] = v4.w;
        }
        __syncthreads();

        // S tile: s[i][j] = sum_e Qs[q][e] * K^T[e][kcol]
        float s[2][4] = {};
#pragma unroll 8
        for (int e = 0; e < 64; ++e) {
            float q0v = Qs[ty * 2 + 0][e];
            float q1v = Qs[ty * 2 + 1][e];
            float4 k4 = *(const float4*)(&KV[e][tx * 4]);
            s[0][0] = fmaf(q0v, k4.x, s[0][0]);
            s[0][1] = fmaf(q0v, k4.y, s[0][1]);
            s[0][2] = fmaf(q0v, k4.z, s[0][2]);
            s[0][3] = fmaf(q0v, k4.w, s[0][3]);
            s[1][0] = fmaf(q1v, k4.x, s[1][0]);
            s[1][1] = fmaf(q1v, k4.y, s[1][1]);
            s[1][2] = fmaf(q1v, k4.z, s[1][2]);
            s[1][3] = fmaf(q1v, k4.w, s[1][3]);
        }

        // mask (int32 per key) + write scores
        {
            int m0v = mk[kc + tx * 4 + 0];
            int m1v = mk[kc + tx * 4 + 1];
            int m2v = mk[kc + tx * 4 + 2];
            int m3v = mk[kc + tx * 4 + 3];
#pragma unroll
            for (int i = 0; i < 2; ++i) {
                float4 sv = make_float4(
                    m0v != 0 ? s[i][0] : -1e30f,
                    m1v != 0 ? s[i][1] : -1e30f,
                    m2v != 0 ? s[i][2] : -1e30f,
                    m3v != 0 ? s[i][3] : -1e30f);
                *(float4*)(&Ss[ty * 2 + i][tx * 4]) = sv;
            }
        }
        __syncthreads();

        // Online softmax: 8 lanes per row, shuffle reduction
        {
            float oldm = mrow[srow];
            float tmax = -1e30f;
#pragma unroll
            for (int c = 0; c < 8; ++c)
                tmax = fmaxf(tmax, Ss[srow][oct * 8 + c]);
            tmax = fmaxf(tmax, __shfl_xor_sync(0xffffffffu, tmax, 1));
            tmax = fmaxf(tmax, __shfl_xor_sync(0xffffffffu, tmax, 2));
            tmax = fmaxf(tmax, __shfl_xor_sync(0xffffffffu, tmax, 4));
            float mnew = fmaxf(oldm, tmax);
            float psum = 0.0f;
#pragma unroll
            for (int c = 0; c < 8; ++c) {
                float p = __expf(Ss[srow][oct * 8 + c] - mnew);
                Ss[srow][oct * 8 + c] = p;
                psum += p;
            }
            psum += __shfl_xor_sync(0xffffffffu, psum, 1);
            psum += __shfl_xor_sync(0xffffffffu, psum, 2);
            psum += __shfl_xor_sync(0xffffffffu, psum, 4);
            if (oct == 0) {
                float f = __expf(oldm - mnew);
                mrow[srow] = mnew;
                frow[srow] = f;
                lrow[srow] = lrow[srow] * f + psum;
            }
        }

        // Load V chunk (natural layout [k][e]) — overwrites KV (reads are done)
        for (int i = tid; i < 64 * 16; i += 256) {
            int row = i >> 4;
            int e4 = (i & 15) * 4;
            *(float4*)(&KV[row][e4]) = *(const float4*)(Vg + (size_t)(kc + row) * DK_ + e4);
        }
        __syncthreads();

        // Rescale accumulator, add P @ V
        {
            float f0 = frow[ty * 2 + 0];
            float f1 = frow[ty * 2 + 1];
#pragma unroll
            for (int j = 0; j < 4; ++j) { oacc[0][j] *= f0; oacc[1][j] *= f1; }
        }
#pragma unroll 8
        for (int kk2 = 0; kk2 < 64; ++kk2) {
            float p0 = Ss[ty * 2 + 0][kk2];
            float p1 = Ss[ty * 2 + 1][kk2];
            float4 v4 = *(const float4*)(&KV[kk2][tx * 4]);
            oacc[0][0] = fmaf(p0, v4.x, oacc[0][0]);
            oacc[0][1] = fmaf(p0, v4.y, oacc[0][1]);
            oacc[0][2] = fmaf(p0, v4.z, oacc[0][2]);
            oacc[0][3] = fmaf(p0, v4.w, oacc[0][3]);
            oacc[1][0] = fmaf(p1, v4.x, oacc[1][0]);
            oacc[1][1] = fmaf(p1, v4.y, oacc[1][1]);
            oacc[1][2] = fmaf(p1, v4.z, oacc[1][2]);
            oacc[1][3] = fmaf(p1, v4.w, oacc[1][3]);
        }
    }

    // Epilogue: normalize and write concat layout
    float* cat = g_cat + ((size_t)b * S_ + q0) * (H_ * DV_) + (size_t)h * DV_;
#pragma unroll
    for (int i = 0; i < 2; ++i) {
        int r = ty * 2 + i;
        float inv = 1.0f / lrow[r];
#pragma unroll
        for (int j = 0; j < 4; ++j)
            cat[(size_t)r * (H_ * DV_) + tx * 4 + j] = oacc[i][j] * inv;
    }
}

// ---------------------------------------------------------------------------
// Kernel 3: output projection.  out[m, n] = sum_c cat[m, c] * Wo[c, n] + bo[n]
// M = B*S = 8192, N = DOUT = 1024, K = H*DV = 1024.
// ---------------------------------------------------------------------------
__global__ __launch_bounds__(256) void out_gemm(
    const float* __restrict__ Wo, const float* __restrict__ bo, float* __restrict__ out)
{
    const int m0 = blockIdx.y * 64;
    const int n0 = blockIdx.x * 64;
    const float* A = g_cat + (size_t)m0 * DOUT_;

    __shared__ float As[16][64];
    __shared__ float Bs[16][64];

    const int tid = threadIdx.x;
    const int tx = tid & 15, ty = tid >> 4;
    const int arow = tid >> 2, aseg = (tid & 3) * 4;
    const int brow = tid >> 4, bseg = (tid & 15) * 4;

    float acc[4][4] = {};

    for (int kk = 0; kk < DOUT_; kk += 16) {
        float4 a4 = *(const float4*)(A + (size_t)arow * DOUT_ + kk + aseg);
        As[aseg + 0][arow] = a4.x;
        As[aseg + 1][arow] = a4.y;
        As[aseg + 2][arow] = a4.z;
        As[aseg + 3][arow] = a4.w;
        *(float4*)(&Bs[brow][bseg]) =
            *(const float4*)(Wo + (size_t)(kk + brow) * DOUT_ + n0 + bseg);
        __syncthreads();
#pragma unroll
        for (int p = 0; p < 16; ++p) {
            float4 a = *(const float4*)(&As[p][ty * 4]);
            float4 bb = *(const float4*)(&Bs[p][tx * 4]);
            float ar[4] = {a.x, a.y, a.z, a.w};
            float br[4] = {bb.x, bb.y, bb.z, bb.w};
#pragma unroll
            for (int i = 0; i < 4; ++i)
#pragma unroll
                for (int j = 0; j < 4; ++j)
                    acc[i][j] = fmaf(ar[i], br[j], acc[i][j]);
        }
        __syncthreads();
    }

#pragma unroll
    for (int i = 0; i < 4; ++i)
#pragma unroll
        for (int j = 0; j < 4; ++j)
            out[(size_t)(m0 + ty * 4 + i) * DOUT_ + n0 + tx * 4 + j] =
                acc[i][j] + bo[n0 + tx * 4 + j];
}

// ---------------------------------------------------------------------------
extern "C" void kernel_launch(void* const* d_in, const int* in_sizes, int n_in,
                              void* d_out, int out_size)
{
    const float* q  = (const float*)d_in[0];
    const float* k  = (const float*)d_in[1];
    const float* v  = (const float*)d_in[2];
    const int* mask = (const int*)d_in[3];
    const float* Wq = (const float*)d_in[4];
    const float* bq = (const float*)d_in[5];
    const float* Wk = (const float*)d_in[6];
    const float* bk = (const float*)d_in[7];
    const float* Wv = (const float*)d_in[8];
    const float* bv = (const float*)d_in[9];
    const float* Wo = (const float*)d_in[10];
    const float* bo = (const float*)d_in[11];
    float* out = (float*)d_out;

    dim3 g1(S_ / 64, B_ * H_, 3);
    proj_kernel<<<g1, 256>>>(q, k, v, Wq, Wk, Wv, bq, bk, bv);

    dim3 g2(S_ / 32, B_ * H_);
    attn_kernel<<<g2, 256>>>(mask);

    dim3 g3(DOUT_ / 64, (B_ * S_) / 64);
    out_gemm<<<g3, 256>>>(Wo, bo, out);
}

// round 4
// speedup vs baseline: 1.3904x; 1.3904x over previous
#include <cuda_runtime.h>
#include <cstdint>

#define B_ 4
#define S_ 2048
#define D_ 1024
#define H_ 16
#define DK_ 64
#define DV_ 64
#define DOUT_ 1024

// Scratch: qh/kh/vh in (b,h,s,e) layout; concat in (b,s,h*DV) layout.
__device__ float g_qh[(size_t)B_*H_*S_*DK_];
__device__ float g_kh[(size_t)B_*H_*S_*DK_];
__device__ float g_vh[(size_t)B_*H_*S_*DV_];
__device__ float g_cat[(size_t)B_*S_*H_*DV_];

// ---------------------------------------------------------------------------
// PTX helpers
// ---------------------------------------------------------------------------
__device__ __forceinline__ uint32_t f2tf(float f) {
    uint32_t u;
    asm("cvt.rna.tf32.f32 %0, %1;" : "=r"(u) : "f"(f));
    return u;
}

__device__ __forceinline__ void mma_tf32(float* d, const uint32_t* a, const uint32_t* b) {
    asm volatile(
        "mma.sync.aligned.m16n8k8.row.col.f32.tf32.tf32.f32 "
        "{%0,%1,%2,%3}, {%4,%5,%6,%7}, {%8,%9}, {%0,%1,%2,%3};\n"
        : "+f"(d[0]), "+f"(d[1]), "+f"(d[2]), "+f"(d[3])
        : "r"(a[0]), "r"(a[1]), "r"(a[2]), "r"(a[3]), "r"(b[0]), "r"(b[1]));
}

__device__ __forceinline__ void cpa16(uint32_t dst, const float* src) {
    asm volatile("cp.async.cg.shared.global [%0], [%1], 16;\n" :: "r"(dst), "l"(src));
}
__device__ __forceinline__ void cpa_commit() {
    asm volatile("cp.async.commit_group;\n");
}
template <int N>
__device__ __forceinline__ void cpa_wait() {
    asm volatile("cp.async.wait_group %0;\n" :: "n"(N));
}

// A smem row stride 20 floats (16 + 4 pad): g*20+tig spans all 32 banks.
// B smem row stride 136 floats (128 + 8 pad): tig*8+g spans all 32 banks.
#define AP 20
#define BP 136

// Compute one BK=16 buffer: warp tile 64(m) x 32(n), 4x4 m16n8k8 frags.
__device__ __forceinline__ void mma_compute16(const float* As, const float* Bs,
                                              float acc[4][4][4],
                                              int wm, int wn, int g, int tig)
{
#pragma unroll
    for (int ks = 0; ks < 2; ++ks) {
        const int kr = ks * 8;
        uint32_t a[4][4];
#pragma unroll
        for (int mf = 0; mf < 4; ++mf) {
            const int m = wm * 64 + mf * 16;
            a[mf][0] = f2tf(As[(m + g)     * AP + kr + tig]);
            a[mf][1] = f2tf(As[(m + g + 8) * AP + kr + tig]);
            a[mf][2] = f2tf(As[(m + g)     * AP + kr + tig + 4]);
            a[mf][3] = f2tf(As[(m + g + 8) * AP + kr + tig + 4]);
        }
        uint32_t b[4][2];
#pragma unroll
        for (int nf = 0; nf < 4; ++nf) {
            const int n = wn * 32 + nf * 8 + g;
            b[nf][0] = f2tf(Bs[(kr + tig)     * BP + n]);
            b[nf][1] = f2tf(Bs[(kr + tig + 4) * BP + n]);
        }
#pragma unroll
        for (int mf = 0; mf < 4; ++mf)
#pragma unroll
            for (int nf = 0; nf < 4; ++nf)
                mma_tf32(acc[mf][nf], a[mf], b[nf]);
    }
}

// ---------------------------------------------------------------------------
// Kernel 1: per-head projections via tf32 mma.
// Block tile: 128 rows (m = b*S+s) x 128 cols (2 heads x 64), K = 1024, BK=16.
// 256 threads = 8 warps, warp grid 2(m) x 4(n), warp tile 64x32.
// ---------------------------------------------------------------------------
__global__ __launch_bounds__(256, 1) void proj_mma(
    const float* __restrict__ q, const float* __restrict__ k, const float* __restrict__ v,
    const float* __restrict__ Wq, const float* __restrict__ Wk, const float* __restrict__ Wv,
    const float* __restrict__ bq, const float* __restrict__ bk, const float* __restrict__ bv)
{
    const int z = blockIdx.z;
    const float* X    = (z == 0) ? q  : (z == 1) ? k  : v;
    const float* W    = (z == 0) ? Wq : (z == 1) ? Wk : Wv;
    const float* bias = (z == 0) ? bq : (z == 1) ? bk : bv;
    float* Out        = (z == 0) ? g_qh : (z == 1) ? g_kh : g_vh;

    const int h0 = blockIdx.y * 2;            // 2 heads per block (n panel)
    const int m0 = blockIdx.x * 128;          // global row = b*S + s
    const int b  = m0 >> 11;
    const int s0 = m0 & (S_ - 1);

    const float* Xb = X + (size_t)m0 * D_;

    __shared__ float As[2][128 * AP];
    __shared__ float Bs[2][16 * BP];

    const int tid = threadIdx.x;
    const int wid = tid >> 5, lane = tid & 31;
    const int wm = wid >> 2, wn = wid & 3;
    const int g = lane >> 2, tig = lane & 3;

    // loader mappings
    const int am = tid >> 1, aj = (tid & 1) * 8;         // A: 128 rows x 16 k
    const int brow = tid >> 4, bcb = (tid & 15) * 8;     // B: 16 rows x 128 n
    const float* bsrc0 = W + (size_t)(h0 + (bcb >> 6)) * (D_ * DK_) + (bcb & 63);

    uint32_t aDst[2], bDst[2];
    aDst[0] = (uint32_t)__cvta_generic_to_shared(&As[0][am * AP + aj]);
    aDst[1] = (uint32_t)__cvta_generic_to_shared(&As[1][am * AP + aj]);
    bDst[0] = (uint32_t)__cvta_generic_to_shared(&Bs[0][brow * BP + bcb]);
    bDst[1] = (uint32_t)__cvta_generic_to_shared(&Bs[1][brow * BP + bcb]);

    float acc[4][4][4] = {};

    // prefetch tile 0
    {
        const float* as = Xb + (size_t)am * D_ + aj;
        cpa16(aDst[0], as);
        cpa16(aDst[0] + 16, as + 4);
        const float* bs = bsrc0 + (size_t)brow * DK_;
        cpa16(bDst[0], bs);
        cpa16(bDst[0] + 16, bs + 4);
        cpa_commit();
    }

    const int NT = D_ / 16;
#pragma unroll 1
    for (int t = 0; t < NT; ++t) {
        if (t + 1 < NT) {
            const int kk = (t + 1) * 16;
            const int bi = (t + 1) & 1;
            const float* as = Xb + (size_t)am * D_ + kk + aj;
            cpa16(aDst[bi], as);
            cpa16(aDst[bi] + 16, as + 4);
            const float* bs = bsrc0 + (size_t)(kk + brow) * DK_;
            cpa16(bDst[bi], bs);
            cpa16(bDst[bi] + 16, bs + 4);
            cpa_commit();
            cpa_wait<1>();
        } else {
            cpa_wait<0>();
        }
        __syncthreads();
        mma_compute16(As[t & 1], Bs[t & 1], acc, wm, wn, g, tig);
        __syncthreads();
    }

    // epilogue: bias add + store to (b,h,s,e) layout
#pragma unroll
    for (int nf = 0; nf < 4; ++nf) {
        const int c = wn * 32 + nf * 8 + tig * 2;
        const int h = h0 + (c >> 6);
        const int e = c & 63;
        const float b0v = bias[h * DK_ + e];
        const float b1v = bias[h * DK_ + e + 1];
        float* Ob = Out + ((size_t)(b * H_ + h) * S_ + s0) * DK_ + e;
#pragma unroll
        for (int mf = 0; mf < 4; ++mf) {
            const int r = wm * 64 + mf * 16 + g;
            *(float2*)(Ob + (size_t)r * DK_) =
                make_float2(acc[mf][nf][0] + b0v, acc[mf][nf][1] + b1v);
            *(float2*)(Ob + (size_t)(r + 8) * DK_) =
                make_float2(acc[mf][nf][2] + b0v, acc[mf][nf][3] + b1v);
        }
    }
}

// ---------------------------------------------------------------------------
// Kernel 2: flash-style attention per (b,h) — unchanged fp32 (R3-passing).
// ---------------------------------------------------------------------------
__global__ __launch_bounds__(256) void attn_kernel(const int* __restrict__ mask)
{
    const int bh = blockIdx.y;
    const int b = bh >> 4, h = bh & 15;
    const int q0 = blockIdx.x * 32;

    const float* Qg = g_qh + ((size_t)bh * S_ + q0) * DK_;
    const float* Kg = g_kh + (size_t)bh * S_ * DK_;
    const float* Vg = g_vh + (size_t)bh * S_ * DK_;
    const int* mk = mask + (size_t)b * S_;

    __shared__ float Qs[32][64];
    __shared__ float KV[64][64];
    __shared__ float Ss[32][64];
    __shared__ float mrow[32], lrow[32], frow[32];

    const int tid = threadIdx.x;
    const int tx = tid & 15, ty = tid >> 4;
    const int srow = tid >> 3, oct = tid & 7;

    for (int i = tid; i < 32 * 16; i += 256) {
        int row = i >> 4;
        int e4 = (i & 15) * 4;
        float4 v4 = *(const float4*)(Qg + (size_t)row * DK_ + e4);
        *(float4*)(&Qs[row][e4]) = make_float4(v4.x * 0.125f, v4.y * 0.125f,
                                               v4.z * 0.125f, v4.w * 0.125f);
    }
    if (tid < 32) { mrow[tid] = -1e30f; lrow[tid] = 0.0f; }

    float oacc[2][4] = {};

    for (int kc = 0; kc < S_; kc += 64) {
        __syncthreads();

        for (int i = tid; i < 64 * 16; i += 256) {
            int row = i & 63;
            int e4 = (i >> 6) * 4;
            float4 v4 = *(const float4*)(Kg + (size_t)(kc + row) * DK_ + e4);
            KV[e4 + 0][row] = v4.x;
            KV[e4 + 1][row] = v4.y;
            KV[e4 + 2][row] = v4.z;
            KV[e4 + 3][row] = v4.w;
        }
        __syncthreads();

        float s[2][4] = {};
#pragma unroll 8
        for (int e = 0; e < 64; ++e) {
            float q0v = Qs[ty * 2 + 0][e];
            float q1v = Qs[ty * 2 + 1][e];
            float4 k4 = *(const float4*)(&KV[e][tx * 4]);
            s[0][0] = fmaf(q0v, k4.x, s[0][0]);
            s[0][1] = fmaf(q0v, k4.y, s[0][1]);
            s[0][2] = fmaf(q0v, k4.z, s[0][2]);
            s[0][3] = fmaf(q0v, k4.w, s[0][3]);
            s[1][0] = fmaf(q1v, k4.x, s[1][0]);
            s[1][1] = fmaf(q1v, k4.y, s[1][1]);
            s[1][2] = fmaf(q1v, k4.z, s[1][2]);
            s[1][3] = fmaf(q1v, k4.w, s[1][3]);
        }

        {
            int m0v = mk[kc + tx * 4 + 0];
            int m1v = mk[kc + tx * 4 + 1];
            int m2v = mk[kc + tx * 4 + 2];
            int m3v = mk[kc + tx * 4 + 3];
#pragma unroll
            for (int i = 0; i < 2; ++i) {
                float4 sv = make_float4(
                    m0v != 0 ? s[i][0] : -1e30f,
                    m1v != 0 ? s[i][1] : -1e30f,
                    m2v != 0 ? s[i][2] : -1e30f,
                    m3v != 0 ? s[i][3] : -1e30f);
                *(float4*)(&Ss[ty * 2 + i][tx * 4]) = sv;
            }
        }
        __syncthreads();

        {
            float oldm = mrow[srow];
            float tmax = -1e30f;
#pragma unroll
            for (int c = 0; c < 8; ++c)
                tmax = fmaxf(tmax, Ss[srow][oct * 8 + c]);
            tmax = fmaxf(tmax, __shfl_xor_sync(0xffffffffu, tmax, 1));
            tmax = fmaxf(tmax, __shfl_xor_sync(0xffffffffu, tmax, 2));
            tmax = fmaxf(tmax, __shfl_xor_sync(0xffffffffu, tmax, 4));
            float mnew = fmaxf(oldm, tmax);
            float psum = 0.0f;
#pragma unroll
            for (int c = 0; c < 8; ++c) {
                float p = __expf(Ss[srow][oct * 8 + c] - mnew);
                Ss[srow][oct * 8 + c] = p;
                psum += p;
            }
            psum += __shfl_xor_sync(0xffffffffu, psum, 1);
            psum += __shfl_xor_sync(0xffffffffu, psum, 2);
            psum += __shfl_xor_sync(0xffffffffu, psum, 4);
            if (oct == 0) {
                float f = __expf(oldm - mnew);
                mrow[srow] = mnew;
                frow[srow] = f;
                lrow[srow] = lrow[srow] * f + psum;
            }
        }

        for (int i = tid; i < 64 * 16; i += 256) {
            int row = i >> 4;
            int e4 = (i & 15) * 4;
            *(float4*)(&KV[row][e4]) = *(const float4*)(Vg + (size_t)(kc + row) * DK_ + e4);
        }
        __syncthreads();

        {
            float f0 = frow[ty * 2 + 0];
            float f1 = frow[ty * 2 + 1];
#pragma unroll
            for (int j = 0; j < 4; ++j) { oacc[0][j] *= f0; oacc[1][j] *= f1; }
        }
#pragma unroll 8
        for (int kk2 = 0; kk2 < 64; ++kk2) {
            float p0 = Ss[ty * 2 + 0][kk2];
            float p1 = Ss[ty * 2 + 1][kk2];
            float4 v4 = *(const float4*)(&KV[kk2][tx * 4]);
            oacc[0][0] = fmaf(p0, v4.x, oacc[0][0]);
            oacc[0][1] = fmaf(p0, v4.y, oacc[0][1]);
            oacc[0][2] = fmaf(p0, v4.z, oacc[0][2]);
            oacc[0][3] = fmaf(p0, v4.w, oacc[0][3]);
            oacc[1][0] = fmaf(p1, v4.x, oacc[1][0]);
            oacc[1][1] = fmaf(p1, v4.y, oacc[1][1]);
            oacc[1][2] = fmaf(p1, v4.z, oacc[1][2]);
            oacc[1][3] = fmaf(p1, v4.w, oacc[1][3]);
        }
    }

    float* cat = g_cat + ((size_t)b * S_ + q0) * (H_ * DV_) + (size_t)h * DV_;
#pragma unroll
    for (int i = 0; i < 2; ++i) {
        int r = ty * 2 + i;
        float inv = 1.0f / lrow[r];
#pragma unroll
        for (int j = 0; j < 4; ++j)
            cat[(size_t)r * (H_ * DV_) + tx * 4 + j] = oacc[i][j] * inv;
    }
}

// ---------------------------------------------------------------------------
// Kernel 3: output projection via tf32 mma.  M=8192, N=1024, K=1024.
// Same tiling as proj_mma; B/bias/output are plain row-major.
// ---------------------------------------------------------------------------
__global__ __launch_bounds__(256, 1) void out_mma(
    const float* __restrict__ Wo, const float* __restrict__ bo, float* __restrict__ out)
{
    const int m0 = blockIdx.x * 128;
    const int n0 = blockIdx.y * 128;

    const float* Ab = g_cat + (size_t)m0 * DOUT_;

    __shared__ float As[2][128 * AP];
    __shared__ float Bs[2][16 * BP];

    const int tid = threadIdx.x;
    const int wid = tid >> 5, lane = tid & 31;
    const int wm = wid >> 2, wn = wid & 3;
    const int g = lane >> 2, tig = lane & 3;

    const int am = tid >> 1, aj = (tid & 1) * 8;
    const int brow = tid >> 4, bcb = (tid & 15) * 8;
    const float* bsrc0 = Wo + n0 + bcb;

    uint32_t aDst[2], bDst[2];
    aDst[0] = (uint32_t)__cvta_generic_to_shared(&As[0][am * AP + aj]);
    aDst[1] = (uint32_t)__cvta_generic_to_shared(&As[1][am * AP + aj]);
    bDst[0] = (uint32_t)__cvta_generic_to_shared(&Bs[0][brow * BP + bcb]);
    bDst[1] = (uint32_t)__cvta_generic_to_shared(&Bs[1][brow * BP + bcb]);

    float acc[4][4][4] = {};

    {
        const float* as = Ab + (size_t)am * DOUT_ + aj;
        cpa16(aDst[0], as);
        cpa16(aDst[0] + 16, as + 4);
        const float* bs = bsrc0 + (size_t)brow * DOUT_;
        cpa16(bDst[0], bs);
        cpa16(bDst[0] + 16, bs + 4);
        cpa_commit();
    }

    const int NT = DOUT_ / 16;
#pragma unroll 1
    for (int t = 0; t < NT; ++t) {
        if (t + 1 < NT) {
            const int kk = (t + 1) * 16;
            const int bi = (t + 1) & 1;
            const float* as = Ab + (size_t)am * DOUT_ + kk + aj;
            cpa16(aDst[bi], as);
            cpa16(aDst[bi] + 16, as + 4);
            const float* bs = bsrc0 + (size_t)(kk + brow) * DOUT_;
            cpa16(bDst[bi], bs);
            cpa16(bDst[bi] + 16, bs + 4);
            cpa_commit();
            cpa_wait<1>();
        } else {
            cpa_wait<0>();
        }
        __syncthreads();
        mma_compute16(As[t & 1], Bs[t & 1], acc, wm, wn, g, tig);
        __syncthreads();
    }

#pragma unroll
    for (int nf = 0; nf < 4; ++nf) {
        const int c = n0 + wn * 32 + nf * 8 + tig * 2;
        const float b0v = bo[c], b1v = bo[c + 1];
#pragma unroll
        for (int mf = 0; mf < 4; ++mf) {
            const int r = m0 + wm * 64 + mf * 16 + g;
            *(float2*)(out + (size_t)r * DOUT_ + c) =
                make_float2(acc[mf][nf][0] + b0v, acc[mf][nf][1] + b1v);
            *(float2*)(out + (size_t)(r + 8) * DOUT_ + c) =
                make_float2(acc[mf][nf][2] + b0v, acc[mf][nf][3] + b1v);
        }
    }
}

// ---------------------------------------------------------------------------
extern "C" void kernel_launch(void* const* d_in, const int* in_sizes, int n_in,
                              void* d_out, int out_size)
{
    const float* q  = (const float*)d_in[0];
    const float* k  = (const float*)d_in[1];
    const float* v  = (const float*)d_in[2];
    const int* mask = (const int*)d_in[3];
    const float* Wq = (const float*)d_in[4];
    const float* bq = (const float*)d_in[5];
    const float* Wk = (const float*)d_in[6];
    const float* bk = (const float*)d_in[7];
    const float* Wv = (const float*)d_in[8];
    const float* bv = (const float*)d_in[9];
    const float* Wo = (const float*)d_in[10];
    const float* bo = (const float*)d_in[11];
    float* out = (float*)d_out;

    dim3 g1((B_ * S_) / 128, H_ / 2, 3);
    proj_mma<<<g1, 256>>>(q, k, v, Wq, Wk, Wv, bq, bk, bv);

    dim3 g2(S_ / 32, B_ * H_);
    attn_kernel<<<g2, 256>>>(mask);

    dim3 g3((B_ * S_) / 128, DOUT_ / 128);
    out_mma<<<g3, 256>>>(Wo, bo, out);
}

// round 7
// speedup vs baseline: 4.3929x; 3.1594x over previous
#include <cuda_runtime.h>
#include <cstdint>

#define B_ 4
#define S_ 2048
#define D_ 1024
#define H_ 16
#define DK_ 64
#define DV_ 64
#define DOUT_ 1024

// Scratch: qh/kh/vh in (b,h,s,e) layout; concat in (b,s,h*DV) layout.
__device__ float g_qh[(size_t)B_*H_*S_*DK_];
__device__ float g_kh[(size_t)B_*H_*S_*DK_];
__device__ float g_vh[(size_t)B_*H_*S_*DV_];
__device__ float g_cat[(size_t)B_*S_*H_*DV_];

// ---------------------------------------------------------------------------
// PTX helpers
// ---------------------------------------------------------------------------
__device__ __forceinline__ uint32_t f2tf(float f) {
    uint32_t u;
    asm("cvt.rna.tf32.f32 %0, %1;" : "=r"(u) : "f"(f));
    return u;
}

__device__ __forceinline__ void mma_tf32(float* d, const uint32_t* a, const uint32_t* b) {
    asm volatile(
        "mma.sync.aligned.m16n8k8.row.col.f32.tf32.tf32.f32 "
        "{%0,%1,%2,%3}, {%4,%5,%6,%7}, {%8,%9}, {%0,%1,%2,%3};\n"
        : "+f"(d[0]), "+f"(d[1]), "+f"(d[2]), "+f"(d[3])
        : "r"(a[0]), "r"(a[1]), "r"(a[2]), "r"(a[3]), "r"(b[0]), "r"(b[1]));
}

__device__ __forceinline__ void cpa16(uint32_t dst, const void* src) {
    asm volatile("cp.async.cg.shared.global [%0], [%1], 16;\n" :: "r"(dst), "l"(src));
}
__device__ __forceinline__ void cpa_commit() {
    asm volatile("cp.async.commit_group;\n");
}
template <int N>
__device__ __forceinline__ void cpa_wait() {
    asm volatile("cp.async.wait_group %0;\n" :: "n"(N));
}

// GEMM smem row strides (floats): A 16+4 pad, B 128+8 pad (bank-conflict-free).
#define AP 20
#define BP 136

// Compute one BK=16 buffer: warp tile 64(m) x 32(n), 4x4 m16n8k8 frags.
__device__ __forceinline__ void mma_compute16(const float* As, const float* Bs,
                                              float acc[4][4][4],
                                              int wm, int wn, int g, int tig)
{
#pragma unroll
    for (int ks = 0; ks < 2; ++ks) {
        const int kr = ks * 8;
        uint32_t a[4][4];
#pragma unroll
        for (int mf = 0; mf < 4; ++mf) {
            const int m = wm * 64 + mf * 16;
            a[mf][0] = f2tf(As[(m + g)     * AP + kr + tig]);
            a[mf][1] = f2tf(As[(m + g + 8) * AP + kr + tig]);
            a[mf][2] = f2tf(As[(m + g)     * AP + kr + tig + 4]);
            a[mf][3] = f2tf(As[(m + g + 8) * AP + kr + tig + 4]);
        }
        uint32_t b[4][2];
#pragma unroll
        for (int nf = 0; nf < 4; ++nf) {
            const int n = wn * 32 + nf * 8 + g;
            b[nf][0] = f2tf(Bs[(kr + tig)     * BP + n]);
            b[nf][1] = f2tf(Bs[(kr + tig + 4) * BP + n]);
        }
#pragma unroll
        for (int mf = 0; mf < 4; ++mf)
#pragma unroll
            for (int nf = 0; nf < 4; ++nf)
                mma_tf32(acc[mf][nf], a[mf], b[nf]);
    }
}

// ---------------------------------------------------------------------------
// Kernel 1: per-head projections via tf32 mma.
// Block tile: 128 rows x 128 cols (2 heads), K=1024, BK=16, double-buffered.
// ---------------------------------------------------------------------------
__global__ __launch_bounds__(256, 2) void proj_mma(
    const float* __restrict__ q, const float* __restrict__ k, const float* __restrict__ v,
    const float* __restrict__ Wq, const float* __restrict__ Wk, const float* __restrict__ Wv,
    const float* __restrict__ bq, const float* __restrict__ bk, const float* __restrict__ bv)
{
    const int z = blockIdx.z;
    const float* X    = (z == 0) ? q  : (z == 1) ? k  : v;
    const float* W    = (z == 0) ? Wq : (z == 1) ? Wk : Wv;
    const float* bias = (z == 0) ? bq : (z == 1) ? bk : bv;
    float* Out        = (z == 0) ? g_qh : (z == 1) ? g_kh : g_vh;

    const int h0 = blockIdx.y * 2;
    const int m0 = blockIdx.x * 128;
    const int b  = m0 >> 11;
    const int s0 = m0 & (S_ - 1);

    const float* Xb = X + (size_t)m0 * D_;

    __shared__ float As[2][128 * AP];
    __shared__ float Bs[2][16 * BP];

    const int tid = threadIdx.x;
    const int wid = tid >> 5, lane = tid & 31;
    const int wm = wid >> 2, wn = wid & 3;
    const int g = lane >> 2, tig = lane & 3;

    const int am = tid >> 1, aj = (tid & 1) * 8;
    const int brow = tid >> 4, bcb = (tid & 15) * 8;
    const float* bsrc0 = W + (size_t)(h0 + (bcb >> 6)) * (D_ * DK_) + (bcb & 63);

    uint32_t aDst[2], bDst[2];
    aDst[0] = (uint32_t)__cvta_generic_to_shared(&As[0][am * AP + aj]);
    aDst[1] = (uint32_t)__cvta_generic_to_shared(&As[1][am * AP + aj]);
    bDst[0] = (uint32_t)__cvta_generic_to_shared(&Bs[0][brow * BP + bcb]);
    bDst[1] = (uint32_t)__cvta_generic_to_shared(&Bs[1][brow * BP + bcb]);

    float acc[4][4][4] = {};

    {
        const float* as = Xb + (size_t)am * D_ + aj;
        cpa16(aDst[0], as);
        cpa16(aDst[0] + 16, as + 4);
        const float* bs = bsrc0 + (size_t)brow * DK_;
        cpa16(bDst[0], bs);
        cpa16(bDst[0] + 16, bs + 4);
        cpa_commit();
    }

    const int NT = D_ / 16;
#pragma unroll 1
    for (int t = 0; t < NT; ++t) {
        if (t + 1 < NT) {
            const int kk = (t + 1) * 16;
            const int bi = (t + 1) & 1;
            const float* as = Xb + (size_t)am * D_ + kk + aj;
            cpa16(aDst[bi], as);
            cpa16(aDst[bi] + 16, as + 4);
            const float* bs = bsrc0 + (size_t)(kk + brow) * DK_;
            cpa16(bDst[bi], bs);
            cpa16(bDst[bi] + 16, bs + 4);
            cpa_commit();
            cpa_wait<1>();
        } else {
            cpa_wait<0>();
        }
        __syncthreads();
        mma_compute16(As[t & 1], Bs[t & 1], acc, wm, wn, g, tig);
        __syncthreads();
    }

#pragma unroll
    for (int nf = 0; nf < 4; ++nf) {
        const int c = wn * 32 + nf * 8 + tig * 2;
        const int h = h0 + (c >> 6);
        const int e = c & 63;
        const float b0v = bias[h * DK_ + e];
        const float b1v = bias[h * DK_ + e + 1];
        float* Ob = Out + ((size_t)(b * H_ + h) * S_ + s0) * DK_ + e;
#pragma unroll
        for (int mf = 0; mf < 4; ++mf) {
            const int r = wm * 64 + mf * 16 + g;
            *(float2*)(Ob + (size_t)r * DK_) =
                make_float2(acc[mf][nf][0] + b0v, acc[mf][nf][1] + b1v);
            *(float2*)(Ob + (size_t)(r + 8) * DK_) =
                make_float2(acc[mf][nf][2] + b0v, acc[mf][nf][3] + b1v);
        }
    }
}

// ---------------------------------------------------------------------------
// Kernel 2: tensor-core flash attention.
// Block: one (b,h), Br=128 queries (8 warps x 16 rows), Bc=64 key chunks.
// QK^T and P@V via tf32 mma; online softmax in log2 domain (exp2f).
// Smem strides audited conflict-free for all fragment access patterns.
// ---------------------------------------------------------------------------
#define QP 68
#define KP 68
#define VP 72
#define PP 68
#define SM_Q 0
#define SM_K (128 * QP)            // 8704
#define SM_V (SM_K + 64 * KP)      // 13056
#define SM_P (SM_V + 64 * VP)      // 17664
#define SM_M (SM_P + 128 * PP)     // 26368 (float index)
#define SMEM_ATTN ((SM_M + 64) * 4)

__global__ __launch_bounds__(256, 2) void attn_mma(const int* __restrict__ mask)
{
    extern __shared__ float sm[];
    float* Qs = sm + SM_Q;
    float* Ks = sm + SM_K;
    float* Vs = sm + SM_V;
    float* Ps = sm + SM_P;
    int*   Ms = (int*)(sm + SM_M);

    const int bh = blockIdx.y;
    const int b = bh >> 4, h = bh & 15;
    const int q0 = blockIdx.x * 128;

    const float* Qg = g_qh + ((size_t)bh * S_ + q0) * DK_;
    const float* Kg = g_kh + (size_t)bh * S_ * DK_;
    const float* Vg = g_vh + (size_t)bh * S_ * DK_;
    const int* mk = mask + (size_t)b * S_;

    const int tid = threadIdx.x;
    const int w = tid >> 5, lane = tid & 31;
    const int g = lane >> 2, t = lane & 3;

    // scale folded with log2(e): softmax done in log2 domain.
    const float qscale = 0.125f * 1.4426950408889634f;

    // Load Q tile (128 x 64), scaled.
    for (int i = tid; i < 2048; i += 256) {
        const int row = i >> 4, c4 = (i & 15) * 4;
        float4 v4 = *(const float4*)(Qg + (size_t)row * DK_ + c4);
        *(float4*)(&Qs[row * QP + c4]) = make_float4(v4.x * qscale, v4.y * qscale,
                                                     v4.z * qscale, v4.w * qscale);
    }

    float oacc[8][4] = {};
    float mold0 = -1e30f, mold1 = -1e30f;
    float lp0 = 0.0f, lp1 = 0.0f;

    const float* qbase = Qs + (w * 16 + g) * QP;
    float* pbase = Ps + (w * 16 + g) * PP;

#pragma unroll 1
    for (int chunk = 0; chunk < S_ / 64; ++chunk) {
        const int kc = chunk * 64;
        __syncthreads();   // prior-iter Ks/Vs/Ms consumers done

        // cp.async K and V chunks (64 x 64 each) + mask.
#pragma unroll
        for (int j = 0; j < 4; ++j) {
            const int idx = tid + j * 256;
            const int row = idx >> 4, c = (idx & 15) * 4;
            cpa16((uint32_t)__cvta_generic_to_shared(&Ks[row * KP + c]),
                  Kg + (size_t)(kc + row) * DK_ + c);
            cpa16((uint32_t)__cvta_generic_to_shared(&Vs[row * VP + c]),
                  Vg + (size_t)(kc + row) * DK_ + c);
        }
        if (tid < 16)
            cpa16((uint32_t)__cvta_generic_to_shared(&Ms[tid * 4]), mk + kc + tid * 4);
        cpa_commit();
        cpa_wait<0>();
        __syncthreads();

        // --- scores: S = Q @ K^T  (warp: 16 rows x 64 keys) ---
        float sc[8][4] = {};
#pragma unroll
        for (int kb = 0; kb < 8; ++kb) {
            uint32_t a[4];
            const float* qr = qbase + kb * 8 + t;
            a[0] = f2tf(qr[0]);
            a[1] = f2tf(qr[8 * QP]);
            a[2] = f2tf(qr[4]);
            a[3] = f2tf(qr[8 * QP + 4]);
#pragma unroll
            for (int nf = 0; nf < 8; ++nf) {
                uint32_t bb[2];
                const float* kr = Ks + (nf * 8 + g) * KP + kb * 8 + t;
                bb[0] = f2tf(kr[0]);
                bb[1] = f2tf(kr[4]);
                mma_tf32(sc[nf], a, bb);
            }
        }

        // --- mask + row max ---
        float tm0 = -1e30f, tm1 = -1e30f;
#pragma unroll
        for (int nf = 0; nf < 8; ++nf) {
            const int ma = Ms[nf * 8 + 2 * t];
            const int mb = Ms[nf * 8 + 2 * t + 1];
            if (!ma) { sc[nf][0] = -1e30f; sc[nf][2] = -1e30f; }
            if (!mb) { sc[nf][1] = -1e30f; sc[nf][3] = -1e30f; }
            tm0 = fmaxf(tm0, fmaxf(sc[nf][0], sc[nf][1]));
            tm1 = fmaxf(tm1, fmaxf(sc[nf][2], sc[nf][3]));
        }
        tm0 = fmaxf(tm0, __shfl_xor_sync(0xffffffffu, tm0, 1));
        tm0 = fmaxf(tm0, __shfl_xor_sync(0xffffffffu, tm0, 2));
        tm1 = fmaxf(tm1, __shfl_xor_sync(0xffffffffu, tm1, 1));
        tm1 = fmaxf(tm1, __shfl_xor_sync(0xffffffffu, tm1, 2));

        const float mn0 = fmaxf(mold0, tm0);
        const float mn1 = fmaxf(mold1, tm1);
        const float f0 = exp2f(mold0 - mn0);
        const float f1 = exp2f(mold1 - mn1);
        mold0 = mn0; mold1 = mn1;

        // --- exp + partial row sums + write P to smem ---
        float cs0 = 0.0f, cs1 = 0.0f;
#pragma unroll
        for (int nf = 0; nf < 8; ++nf) {
            const float p0 = exp2f(sc[nf][0] - mn0);
            const float p1 = exp2f(sc[nf][1] - mn0);
            const float p2 = exp2f(sc[nf][2] - mn1);
            const float p3 = exp2f(sc[nf][3] - mn1);
            cs0 += p0 + p1;
            cs1 += p2 + p3;
            float* pr = pbase + nf * 8 + 2 * t;
            *(float2*)pr = make_float2(p0, p1);
            *(float2*)(pr + 8 * PP) = make_float2(p2, p3);
        }
        lp0 = lp0 * f0 + cs0;
        lp1 = lp1 * f1 + cs1;

        // rescale output accumulator
#pragma unroll
        for (int nf = 0; nf < 8; ++nf) {
            oacc[nf][0] *= f0; oacc[nf][1] *= f0;
            oacc[nf][2] *= f1; oacc[nf][3] *= f1;
        }
        __syncwarp();   // P rows are warp-private; smem visibility within warp

        // --- O += P @ V ---
#pragma unroll
        for (int kb = 0; kb < 8; ++kb) {
            uint32_t a[4];
            const float* pr = pbase + kb * 8 + t;
            a[0] = f2tf(pr[0]);
            a[1] = f2tf(pr[8 * PP]);
            a[2] = f2tf(pr[4]);
            a[3] = f2tf(pr[8 * PP + 4]);
#pragma unroll
            for (int nf = 0; nf < 8; ++nf) {
                uint32_t bb[2];
                const float* vr = Vs + (kb * 8 + t) * VP + nf * 8 + g;
                bb[0] = f2tf(vr[0]);
                bb[1] = f2tf(vr[4 * VP]);
                mma_tf32(oacc[nf], a, bb);
            }
        }
    }

    // --- epilogue: quad-reduce l, normalize, write concat ---
    lp0 += __shfl_xor_sync(0xffffffffu, lp0, 1);
    lp0 += __shfl_xor_sync(0xffffffffu, lp0, 2);
    lp1 += __shfl_xor_sync(0xffffffffu, lp1, 1);
    lp1 += __shfl_xor_sync(0xffffffffu, lp1, 2);
    const float inv0 = 1.0f / lp0;
    const float inv1 = 1.0f / lp1;

    const int r0 = q0 + w * 16 + g;
    float* cat0 = g_cat + ((size_t)b * S_ + r0) * (H_ * DV_) + (size_t)h * DV_;
    float* cat1 = cat0 + (size_t)8 * (H_ * DV_);
#pragma unroll
    for (int nf = 0; nf < 8; ++nf) {
        const int c = nf * 8 + 2 * t;
        *(float2*)(cat0 + c) = make_float2(oacc[nf][0] * inv0, oacc[nf][1] * inv0);
        *(float2*)(cat1 + c) = make_float2(oacc[nf][2] * inv1, oacc[nf][3] * inv1);
    }
}

// ---------------------------------------------------------------------------
// Kernel 3: output projection via tf32 mma.  M=8192, N=1024, K=1024.
// ---------------------------------------------------------------------------
__global__ __launch_bounds__(256, 2) void out_mma(
    const float* __restrict__ Wo, const float* __restrict__ bo, float* __restrict__ out)
{
    const int m0 = blockIdx.x * 128;
    const int n0 = blockIdx.y * 128;

    const float* Ab = g_cat + (size_t)m0 * DOUT_;

    __shared__ float As[2][128 * AP];
    __shared__ float Bs[2][16 * BP];

    const int tid = threadIdx.x;
    const int wid = tid >> 5, lane = tid & 31;
    const int wm = wid >> 2, wn = wid & 3;
    const int g = lane >> 2, tig = lane & 3;

    const int am = tid >> 1, aj = (tid & 1) * 8;
    const int brow = tid >> 4, bcb = (tid & 15) * 8;
    const float* bsrc0 = Wo + n0 + bcb;

    uint32_t aDst[2], bDst[2];
    aDst[0] = (uint32_t)__cvta_generic_to_shared(&As[0][am * AP + aj]);
    aDst[1] = (uint32_t)__cvta_generic_to_shared(&As[1][am * AP + aj]);
    bDst[0] = (uint32_t)__cvta_generic_to_shared(&Bs[0][brow * BP + bcb]);
    bDst[1] = (uint32_t)__cvta_generic_to_shared(&Bs[1][brow * BP + bcb]);

    float acc[4][4][4] = {};

    {
        const float* as = Ab + (size_t)am * DOUT_ + aj;
        cpa16(aDst[0], as);
        cpa16(aDst[0] + 16, as + 4);
        const float* bs = bsrc0 + (size_t)brow * DOUT_;
        cpa16(bDst[0], bs);
        cpa16(bDst[0] + 16, bs + 4);
        cpa_commit();
    }

    const int NT = DOUT_ / 16;
#pragma unroll 1
    for (int t = 0; t < NT; ++t) {
        if (t + 1 < NT) {
            const int kk = (t + 1) * 16;
            const int bi = (t + 1) & 1;
            const float* as = Ab + (size_t)am * DOUT_ + kk + aj;
            cpa16(aDst[bi], as);
            cpa16(aDst[bi] + 16, as + 4);
            const float* bs = bsrc0 + (size_t)(kk + brow) * DOUT_;
            cpa16(bDst[bi], bs);
            cpa16(bDst[bi] + 16, bs + 4);
            cpa_commit();
            cpa_wait<1>();
        } else {
            cpa_wait<0>();
        }
        __syncthreads();
        mma_compute16(As[t & 1], Bs[t & 1], acc, wm, wn, g, tig);
        __syncthreads();
    }

#pragma unroll
    for (int nf = 0; nf < 4; ++nf) {
        const int c = n0 + wn * 32 + nf * 8 + tig * 2;
        const float b0v = bo[c], b1v = bo[c + 1];
#pragma unroll
        for (int mf = 0; mf < 4; ++mf) {
            const int r = m0 + wm * 64 + mf * 16 + g;
            *(float2*)(out + (size_t)r * DOUT_ + c) =
                make_float2(acc[mf][nf][0] + b0v, acc[mf][nf][1] + b1v);
            *(float2*)(out + (size_t)(r + 8) * DOUT_ + c) =
                make_float2(acc[mf][nf][2] + b0v, acc[mf][nf][3] + b1v);
        }
    }
}

// ---------------------------------------------------------------------------
extern "C" void kernel_launch(void* const* d_in, const int* in_sizes, int n_in,
                              void* d_out, int out_size)
{
    const float* q  = (const float*)d_in[0];
    const float* k  = (const float*)d_in[1];
    const float* v  = (const float*)d_in[2];
    const int* mask = (const int*)d_in[3];
    const float* Wq = (const float*)d_in[4];
    const float* bq = (const float*)d_in[5];
    const float* Wk = (const float*)d_in[6];
    const float* bk = (const float*)d_in[7];
    const float* Wv = (const float*)d_in[8];
    const float* bv = (const float*)d_in[9];
    const float* Wo = (const float*)d_in[10];
    const float* bo = (const float*)d_in[11];
    float* out = (float*)d_out;

    cudaFuncSetAttribute(attn_mma, cudaFuncAttributeMaxDynamicSharedMemorySize, SMEM_ATTN);

    dim3 g1((B_ * S_) / 128, H_ / 2, 3);
    proj_mma<<<g1, 256>>>(q, k, v, Wq, Wk, Wv, bq, bk, bv);

    dim3 g2(S_ / 128, B_ * H_);
    attn_mma<<<g2, 256, SMEM_ATTN>>>(mask);

    dim3 g3((B_ * S_) / 128, DOUT_ / 128);
    out_mma<<<g3, 256>>>(Wo, bo, out);
}

// round 8
// speedup vs baseline: 4.6778x; 1.0649x over previous
#include <cuda_runtime.h>
#include <cstdint>

#define B_ 4
#define S_ 2048
#define D_ 1024
#define H_ 16
#define DK_ 64
#define DV_ 64
#define DOUT_ 1024

// Scratch: qh/kh/vh in (b,h,s,e) layout; concat in (b,s,h*DV) layout.
__device__ float g_qh[(size_t)B_*H_*S_*DK_];
__device__ float g_kh[(size_t)B_*H_*S_*DK_];
__device__ float g_vh[(size_t)B_*H_*S_*DV_];
__device__ float g_cat[(size_t)B_*S_*H_*DV_];

// ---------------------------------------------------------------------------
// PTX helpers
// ---------------------------------------------------------------------------
__device__ __forceinline__ uint32_t f2tf(float f) {
    uint32_t u;
    asm("cvt.rna.tf32.f32 %0, %1;" : "=r"(u) : "f"(f));
    return u;
}

__device__ __forceinline__ void mma_tf32(float* d, const uint32_t* a, const uint32_t* b) {
    asm volatile(
        "mma.sync.aligned.m16n8k8.row.col.f32.tf32.tf32.f32 "
        "{%0,%1,%2,%3}, {%4,%5,%6,%7}, {%8,%9}, {%0,%1,%2,%3};\n"
        : "+f"(d[0]), "+f"(d[1]), "+f"(d[2]), "+f"(d[3])
        : "r"(a[0]), "r"(a[1]), "r"(a[2]), "r"(a[3]), "r"(b[0]), "r"(b[1]));
}

__device__ __forceinline__ void cpa16(uint32_t dst, const void* src) {
    asm volatile("cp.async.cg.shared.global [%0], [%1], 16;\n" :: "r"(dst), "l"(src));
}
__device__ __forceinline__ void cpa_commit() {
    asm volatile("cp.async.commit_group;\n");
}
template <int N>
__device__ __forceinline__ void cpa_wait() {
    asm volatile("cp.async.wait_group %0;\n" :: "n"(N));
}

// GEMM smem row strides (floats): A 16+4 pad, B 128+8 pad (bank-conflict-free).
#define AP 20
#define BP 136

// Compute one BK=16 buffer: warp tile 64(m) x 32(n), 4x4 m16n8k8 frags.
__device__ __forceinline__ void mma_compute16(const float* As, const float* Bs,
                                              float acc[4][4][4],
                                              int wm, int wn, int g, int tig)
{
#pragma unroll
    for (int ks = 0; ks < 2; ++ks) {
        const int kr = ks * 8;
        uint32_t a[4][4];
#pragma unroll
        for (int mf = 0; mf < 4; ++mf) {
            const int m = wm * 64 + mf * 16;
            a[mf][0] = f2tf(As[(m + g)     * AP + kr + tig]);
            a[mf][1] = f2tf(As[(m + g + 8) * AP + kr + tig]);
            a[mf][2] = f2tf(As[(m + g)     * AP + kr + tig + 4]);
            a[mf][3] = f2tf(As[(m + g + 8) * AP + kr + tig + 4]);
        }
        uint32_t b[4][2];
#pragma unroll
        for (int nf = 0; nf < 4; ++nf) {
            const int n = wn * 32 + nf * 8 + g;
            b[nf][0] = f2tf(Bs[(kr + tig)     * BP + n]);
            b[nf][1] = f2tf(Bs[(kr + tig + 4) * BP + n]);
        }
#pragma unroll
        for (int mf = 0; mf < 4; ++mf)
#pragma unroll
            for (int nf = 0; nf < 4; ++nf)
                mma_tf32(acc[mf][nf], a[mf], b[nf]);
    }
}

// ---------------------------------------------------------------------------
// Kernel 1: per-head projections via tf32 mma.
// Block tile: 128 rows x 128 cols (2 heads), K=1024, BK=16, double-buffered.
// ---------------------------------------------------------------------------
__global__ __launch_bounds__(256, 2) void proj_mma(
    const float* __restrict__ q, const float* __restrict__ k, const float* __restrict__ v,
    const float* __restrict__ Wq, const float* __restrict__ Wk, const float* __restrict__ Wv,
    const float* __restrict__ bq, const float* __restrict__ bk, const float* __restrict__ bv)
{
    const int z = blockIdx.z;
    const float* X    = (z == 0) ? q  : (z == 1) ? k  : v;
    const float* W    = (z == 0) ? Wq : (z == 1) ? Wk : Wv;
    const float* bias = (z == 0) ? bq : (z == 1) ? bk : bv;
    float* Out        = (z == 0) ? g_qh : (z == 1) ? g_kh : g_vh;

    const int h0 = blockIdx.y * 2;
    const int m0 = blockIdx.x * 128;
    const int b  = m0 >> 11;
    const int s0 = m0 & (S_ - 1);

    const float* Xb = X + (size_t)m0 * D_;

    __shared__ float As[2][128 * AP];
    __shared__ float Bs[2][16 * BP];

    const int tid = threadIdx.x;
    const int wid = tid >> 5, lane = tid & 31;
    const int wm = wid >> 2, wn = wid & 3;
    const int g = lane >> 2, tig = lane & 3;

    const int am = tid >> 1, aj = (tid & 1) * 8;
    const int brow = tid >> 4, bcb = (tid & 15) * 8;
    const float* bsrc0 = W + (size_t)(h0 + (bcb >> 6)) * (D_ * DK_) + (bcb & 63);

    uint32_t aDst[2], bDst[2];
    aDst[0] = (uint32_t)__cvta_generic_to_shared(&As[0][am * AP + aj]);
    aDst[1] = (uint32_t)__cvta_generic_to_shared(&As[1][am * AP + aj]);
    bDst[0] = (uint32_t)__cvta_generic_to_shared(&Bs[0][brow * BP + bcb]);
    bDst[1] = (uint32_t)__cvta_generic_to_shared(&Bs[1][brow * BP + bcb]);

    float acc[4][4][4] = {};

    {
        const float* as = Xb + (size_t)am * D_ + aj;
        cpa16(aDst[0], as);
        cpa16(aDst[0] + 16, as + 4);
        const float* bs = bsrc0 + (size_t)brow * DK_;
        cpa16(bDst[0], bs);
        cpa16(bDst[0] + 16, bs + 4);
        cpa_commit();
    }

    const int NT = D_ / 16;
#pragma unroll 1
    for (int t = 0; t < NT; ++t) {
        if (t + 1 < NT) {
            const int kk = (t + 1) * 16;
            const int bi = (t + 1) & 1;
            const float* as = Xb + (size_t)am * D_ + kk + aj;
            cpa16(aDst[bi], as);
            cpa16(aDst[bi] + 16, as + 4);
            const float* bs = bsrc0 + (size_t)(kk + brow) * DK_;
            cpa16(bDst[bi], bs);
            cpa16(bDst[bi] + 16, bs + 4);
            cpa_commit();
            cpa_wait<1>();
        } else {
            cpa_wait<0>();
        }
        __syncthreads();
        mma_compute16(As[t & 1], Bs[t & 1], acc, wm, wn, g, tig);
        __syncthreads();
    }

#pragma unroll
    for (int nf = 0; nf < 4; ++nf) {
        const int c = wn * 32 + nf * 8 + tig * 2;
        const int h = h0 + (c >> 6);
        const int e = c & 63;
        const float b0v = bias[h * DK_ + e];
        const float b1v = bias[h * DK_ + e + 1];
        float* Ob = Out + ((size_t)(b * H_ + h) * S_ + s0) * DK_ + e;
#pragma unroll
        for (int mf = 0; mf < 4; ++mf) {
            const int r = wm * 64 + mf * 16 + g;
            *(float2*)(Ob + (size_t)r * DK_) =
                make_float2(acc[mf][nf][0] + b0v, acc[mf][nf][1] + b1v);
            *(float2*)(Ob + (size_t)(r + 8) * DK_) =
                make_float2(acc[mf][nf][2] + b0v, acc[mf][nf][3] + b1v);
        }
    }
}

// ---------------------------------------------------------------------------
// Kernel 2: tensor-core flash attention, R8:
//  - Q pre-converted to tf32 bits in smem (cvt once).
//  - P re-fragmentation via quad shuffles (no smem round-trip, bit-exact).
//  - K/V/mask double-buffered with cp.async (load overlaps compute).
// Block: one (b,h), Br=128 (8 warps x 16 rows), Bc=64.
// ---------------------------------------------------------------------------
#define QP 68
#define KP 68
#define VP 72
#define KBUF (64 * KP)             // 4352
#define VBUF (64 * VP)             // 4608
#define SM_K (128 * QP)            // 8704
#define SM_V (SM_K + 2 * KBUF)     // 17408
#define SM_M (SM_V + 2 * VBUF)     // 26624 (float index)
#define SMEM_ATTN ((SM_M + 128) * 4)

__global__ __launch_bounds__(256, 2) void attn_mma(const int* __restrict__ mask)
{
    extern __shared__ float sm[];
    uint32_t* Qs = (uint32_t*)sm;          // tf32 bits
    float* Ks = sm + SM_K;                 // 2 buffers
    float* Vs = sm + SM_V;                 // 2 buffers
    int*   Ms = (int*)(sm + SM_M);         // 2 buffers of 64

    const int bh = blockIdx.y;
    const int b = bh >> 4, h = bh & 15;
    const int q0 = blockIdx.x * 128;

    const float* Qg = g_qh + ((size_t)bh * S_ + q0) * DK_;
    const float* Kg = g_kh + (size_t)bh * S_ * DK_;
    const float* Vg = g_vh + (size_t)bh * S_ * DK_;
    const int* mk = mask + (size_t)b * S_;

    const int tid = threadIdx.x;
    const int w = tid >> 5, lane = tid & 31;
    const int g = lane >> 2, t = lane & 3;
    const int lo = t & 1;                   // odd lane-in-pair selector
    const int sh = t >> 1, sh2 = sh + 2;    // quad shuffle sources

    // scale folded with log2(e): softmax in log2 domain.
    const float qscale = 0.125f * 1.4426950408889634f;

    // Load Q (128 x 64), scale + convert to tf32 bits once.
    for (int i = tid; i < 2048; i += 256) {
        const int row = i >> 4, c4 = (i & 15) * 4;
        float4 v4 = *(const float4*)(Qg + (size_t)row * DK_ + c4);
        uint4 u;
        u.x = f2tf(v4.x * qscale);
        u.y = f2tf(v4.y * qscale);
        u.z = f2tf(v4.z * qscale);
        u.w = f2tf(v4.w * qscale);
        *(uint4*)(&Qs[row * QP + c4]) = u;
    }

    // prologue: issue chunk 0 loads into buffer 0
    {
#pragma unroll
        for (int j = 0; j < 4; ++j) {
            const int idx = tid + j * 256;
            const int row = idx >> 4, c = (idx & 15) * 4;
            cpa16((uint32_t)__cvta_generic_to_shared(&Ks[row * KP + c]),
                  Kg + (size_t)row * DK_ + c);
            cpa16((uint32_t)__cvta_generic_to_shared(&Vs[row * VP + c]),
                  Vg + (size_t)row * DK_ + c);
        }
        if (tid < 16)
            cpa16((uint32_t)__cvta_generic_to_shared(&Ms[tid * 4]), mk + tid * 4);
        cpa_commit();
    }

    float oacc[8][4] = {};
    float mold0 = -1e30f, mold1 = -1e30f;
    float lp0 = 0.0f, lp1 = 0.0f;

    const uint32_t* qbase = Qs + (w * 16 + g) * QP;

    const int NCH = S_ / 64;
#pragma unroll 1
    for (int chunk = 0; chunk < NCH; ++chunk) {
        const int bi = chunk & 1;

        if (chunk + 1 < NCH) {
            const int kc = (chunk + 1) * 64;
            const int bo2 = bi ^ 1;
            float* kd = Ks + bo2 * KBUF;
            float* vd = Vs + bo2 * VBUF;
#pragma unroll
            for (int j = 0; j < 4; ++j) {
                const int idx = tid + j * 256;
                const int row = idx >> 4, c = (idx & 15) * 4;
                cpa16((uint32_t)__cvta_generic_to_shared(&kd[row * KP + c]),
                      Kg + (size_t)(kc + row) * DK_ + c);
                cpa16((uint32_t)__cvta_generic_to_shared(&vd[row * VP + c]),
                      Vg + (size_t)(kc + row) * DK_ + c);
            }
            if (tid < 16)
                cpa16((uint32_t)__cvta_generic_to_shared(&Ms[bo2 * 64 + tid * 4]),
                      mk + kc + tid * 4);
            cpa_commit();
            cpa_wait<1>();
        } else {
            cpa_wait<0>();
        }
        __syncthreads();

        const float* Kb = Ks + bi * KBUF;
        const float* Vb = Vs + bi * VBUF;
        const int*   Mb = Ms + bi * 64;

        // --- scores: S = Q @ K^T ---
        float sc[8][4] = {};
#pragma unroll
        for (int kb = 0; kb < 8; ++kb) {
            uint32_t a[4];
            const uint32_t* qr = qbase + kb * 8 + t;
            a[0] = qr[0];
            a[1] = qr[8 * QP];
            a[2] = qr[4];
            a[3] = qr[8 * QP + 4];
#pragma unroll
            for (int nf = 0; nf < 8; ++nf) {
                uint32_t bb[2];
                const float* kr = Kb + (nf * 8 + g) * KP + kb * 8 + t;
                bb[0] = f2tf(kr[0]);
                bb[1] = f2tf(kr[4]);
                mma_tf32(sc[nf], a, bb);
            }
        }

        // --- mask + row max ---
        float tm0 = -1e30f, tm1 = -1e30f;
#pragma unroll
        for (int nf = 0; nf < 8; ++nf) {
            const int ma = Mb[nf * 8 + 2 * t];
            const int mb = Mb[nf * 8 + 2 * t + 1];
            if (!ma) { sc[nf][0] = -1e30f; sc[nf][2] = -1e30f; }
            if (!mb) { sc[nf][1] = -1e30f; sc[nf][3] = -1e30f; }
            tm0 = fmaxf(tm0, fmaxf(sc[nf][0], sc[nf][1]));
            tm1 = fmaxf(tm1, fmaxf(sc[nf][2], sc[nf][3]));
        }
        tm0 = fmaxf(tm0, __shfl_xor_sync(0xffffffffu, tm0, 1));
        tm0 = fmaxf(tm0, __shfl_xor_sync(0xffffffffu, tm0, 2));
        tm1 = fmaxf(tm1, __shfl_xor_sync(0xffffffffu, tm1, 1));
        tm1 = fmaxf(tm1, __shfl_xor_sync(0xffffffffu, tm1, 2));

        const float mn0 = fmaxf(mold0, tm0);
        const float mn1 = fmaxf(mold1, tm1);
        const float f0 = exp2f(mold0 - mn0);
        const float f1 = exp2f(mold1 - mn1);
        mold0 = mn0; mold1 = mn1;

        // --- exp + partial sums; overwrite sc with tf32 bits of P ---
        float cs0 = 0.0f, cs1 = 0.0f;
#pragma unroll
        for (int nf = 0; nf < 8; ++nf) {
            const float p0 = exp2f(sc[nf][0] - mn0);
            const float p1 = exp2f(sc[nf][1] - mn0);
            const float p2 = exp2f(sc[nf][2] - mn1);
            const float p3 = exp2f(sc[nf][3] - mn1);
            cs0 += p0 + p1;
            cs1 += p2 + p3;
            sc[nf][0] = __uint_as_float(f2tf(p0));
            sc[nf][1] = __uint_as_float(f2tf(p1));
            sc[nf][2] = __uint_as_float(f2tf(p2));
            sc[nf][3] = __uint_as_float(f2tf(p3));
        }
        lp0 = lp0 * f0 + cs0;
        lp1 = lp1 * f1 + cs1;

        // rescale output accumulator
#pragma unroll
        for (int nf = 0; nf < 8; ++nf) {
            oacc[nf][0] *= f0; oacc[nf][1] *= f0;
            oacc[nf][2] *= f1; oacc[nf][3] *= f1;
        }

        // --- O += P @ V ;  P C-frag -> A-frag via quad shuffles (bit-exact) ---
#pragma unroll
        for (int kb = 0; kb < 8; ++kb) {
            const uint32_t u0 = __float_as_uint(sc[kb][0]);
            const uint32_t u1 = __float_as_uint(sc[kb][1]);
            const uint32_t u2 = __float_as_uint(sc[kb][2]);
            const uint32_t u3 = __float_as_uint(sc[kb][3]);
            uint32_t a[4];
            {
                const uint32_t x0 = __shfl_sync(0xffffffffu, u0, sh, 4);
                const uint32_t x1 = __shfl_sync(0xffffffffu, u1, sh, 4);
                a[0] = lo ? x1 : x0;                       // P[g][kb8+t]
                const uint32_t x2 = __shfl_sync(0xffffffffu, u2, sh, 4);
                const uint32_t x3 = __shfl_sync(0xffffffffu, u3, sh, 4);
                a[1] = lo ? x3 : x2;                       // P[g+8][kb8+t]
                const uint32_t y0 = __shfl_sync(0xffffffffu, u0, sh2, 4);
                const uint32_t y1 = __shfl_sync(0xffffffffu, u1, sh2, 4);
                a[2] = lo ? y1 : y0;                       // P[g][kb8+t+4]
                const uint32_t y2 = __shfl_sync(0xffffffffu, u2, sh2, 4);
                const uint32_t y3 = __shfl_sync(0xffffffffu, u3, sh2, 4);
                a[3] = lo ? y3 : y2;                       // P[g+8][kb8+t+4]
            }
#pragma unroll
            for (int nf = 0; nf < 8; ++nf) {
                uint32_t bb[2];
                const float* vr = Vb + (kb * 8 + t) * VP + nf * 8 + g;
                bb[0] = f2tf(vr[0]);
                bb[1] = f2tf(vr[4 * VP]);
                mma_tf32(oacc[nf], a, bb);
            }
        }
        __syncthreads();   // all warps done with buf bi before it is overwritten
    }

    // --- epilogue: quad-reduce l, normalize, write concat ---
    lp0 += __shfl_xor_sync(0xffffffffu, lp0, 1);
    lp0 += __shfl_xor_sync(0xffffffffu, lp0, 2);
    lp1 += __shfl_xor_sync(0xffffffffu, lp1, 1);
    lp1 += __shfl_xor_sync(0xffffffffu, lp1, 2);
    const float inv0 = 1.0f / lp0;
    const float inv1 = 1.0f / lp1;

    const int r0 = q0 + w * 16 + g;
    float* cat0 = g_cat + ((size_t)b * S_ + r0) * (H_ * DV_) + (size_t)h * DV_;
    float* cat1 = cat0 + (size_t)8 * (H_ * DV_);
#pragma unroll
    for (int nf = 0; nf < 8; ++nf) {
        const int c = nf * 8 + 2 * t;
        *(float2*)(cat0 + c) = make_float2(oacc[nf][0] * inv0, oacc[nf][1] * inv0);
        *(float2*)(cat1 + c) = make_float2(oacc[nf][2] * inv1, oacc[nf][3] * inv1);
    }
}

// ---------------------------------------------------------------------------
// Kernel 3: output projection via tf32 mma.  M=8192, N=1024, K=1024.
// ---------------------------------------------------------------------------
__global__ __launch_bounds__(256, 2) void out_mma(
    const float* __restrict__ Wo, const float* __restrict__ bo, float* __restrict__ out)
{
    const int m0 = blockIdx.x * 128;
    const int n0 = blockIdx.y * 128;

    const float* Ab = g_cat + (size_t)m0 * DOUT_;

    __shared__ float As[2][128 * AP];
    __shared__ float Bs[2][16 * BP];

    const int tid = threadIdx.x;
    const int wid = tid >> 5, lane = tid & 31;
    const int wm = wid >> 2, wn = wid & 3;
    const int g = lane >> 2, tig = lane & 3;

    const int am = tid >> 1, aj = (tid & 1) * 8;
    const int brow = tid >> 4, bcb = (tid & 15) * 8;
    const float* bsrc0 = Wo + n0 + bcb;

    uint32_t aDst[2], bDst[2];
    aDst[0] = (uint32_t)__cvta_generic_to_shared(&As[0][am * AP + aj]);
    aDst[1] = (uint32_t)__cvta_generic_to_shared(&As[1][am * AP + aj]);
    bDst[0] = (uint32_t)__cvta_generic_to_shared(&Bs[0][brow * BP + bcb]);
    bDst[1] = (uint32_t)__cvta_generic_to_shared(&Bs[1][brow * BP + bcb]);

    float acc[4][4][4] = {};

    {
        const float* as = Ab + (size_t)am * DOUT_ + aj;
        cpa16(aDst[0], as);
        cpa16(aDst[0] + 16, as + 4);
        const float* bs = bsrc0 + (size_t)brow * DOUT_;
        cpa16(bDst[0], bs);
        cpa16(bDst[0] + 16, bs + 4);
        cpa_commit();
    }

    const int NT = DOUT_ / 16;
#pragma unroll 1
    for (int t = 0; t < NT; ++t) {
        if (t + 1 < NT) {
            const int kk = (t + 1) * 16;
            const int bi = (t + 1) & 1;
            const float* as = Ab + (size_t)am * DOUT_ + kk + aj;
            cpa16(aDst[bi], as);
            cpa16(aDst[bi] + 16, as + 4);
            const float* bs = bsrc0 + (size_t)(kk + brow) * DOUT_;
            cpa16(bDst[bi], bs);
            cpa16(bDst[bi] + 16, bs + 4);
            cpa_commit();
            cpa_wait<1>();
        } else {
            cpa_wait<0>();
        }
        __syncthreads();
        mma_compute16(As[t & 1], Bs[t & 1], acc, wm, wn, g, tig);
        __syncthreads();
    }

#pragma unroll
    for (int nf = 0; nf < 4; ++nf) {
        const int c = n0 + wn * 32 + nf * 8 + tig * 2;
        const float b0v = bo[c], b1v = bo[c + 1];
#pragma unroll
        for (int mf = 0; mf < 4; ++mf) {
            const int r = m0 + wm * 64 + mf * 16 + g;
            *(float2*)(out + (size_t)r * DOUT_ + c) =
                make_float2(acc[mf][nf][0] + b0v, acc[mf][nf][1] + b1v);
            *(float2*)(out + (size_t)(r + 8) * DOUT_ + c) =
                make_float2(acc[mf][nf][2] + b0v, acc[mf][nf][3] + b1v);
        }
    }
}

// ---------------------------------------------------------------------------
extern "C" void kernel_launch(void* const* d_in, const int* in_sizes, int n_in,
                              void* d_out, int out_size)
{
    const float* q  = (const float*)d_in[0];
    const float* k  = (const float*)d_in[1];
    const float* v  = (const float*)d_in[2];
    const int* mask = (const int*)d_in[3];
    const float* Wq = (const float*)d_in[4];
    const float* bq = (const float*)d_in[5];
    const float* Wk = (const float*)d_in[6];
    const float* bk = (const float*)d_in[7];
    const float* Wv = (const float*)d_in[8];
    const float* bv = (const float*)d_in[9];
    const float* Wo = (const float*)d_in[10];
    const float* bo = (const float*)d_in[11];
    float* out = (float*)d_out;

    cudaFuncSetAttribute(attn_mma, cudaFuncAttributeMaxDynamicSharedMemorySize, SMEM_ATTN);

    dim3 g1((B_ * S_) / 128, H_ / 2, 3);
    proj_mma<<<g1, 256>>>(q, k, v, Wq, Wk, Wv, bq, bk, bv);

    dim3 g2(S_ / 128, B_ * H_);
    attn_mma<<<g2, 256, SMEM_ATTN>>>(mask);

    dim3 g3((B_ * S_) / 128, DOUT_ / 128);
    out_mma<<<g3, 256>>>(Wo, bo, out);
}